// round 14
// baseline (speedup 1.0000x reference)
#include <cuda_runtime.h>

#define TW 32
#define TH 64
#define IH 74          // TH + 10
#define HS 36          // map-pair stride in ull (float2) units; 288B rows
#define HMAP (IH*HS)   // ulls per map-pair
#define NBLOCKS (16*8*96)
#define SSIM_C1 (0.01f*0.01f)
#define SSIM_C2 (0.03f*0.03f)

typedef unsigned long long ull;

__device__ double g_accum = 0.0;
__device__ unsigned int g_count = 0u;

// Gaussian(sigma=1.5, ws=11) 1-D half-weights (symmetric), normalized.
#define W0 0.00102838f
#define W1 0.00759880f
#define W2 0.03600077f
#define W3 0.10936069f
#define W4 0.21300553f
#define W5 0.26601172f

#define FMA2(acc, a, b) asm("fma.rn.f32x2 %0, %1, %2, %0;" : "+l"(acc) : "l"(a), "l"(b))
#define SQ2(x)          asm("mul.rn.f32x2 %0, %0, %0;"     : "+l"(x))
#define PACK2(dst, lo, hi) asm("mov.b64 %0, {%1, %2};" : "=l"(dst) : "f"(lo), "f"(hi))

struct StageACtx {
    const float* p1;
    const float* p2;
    ull* hSD;
    ull* hPQ;
    int x0, y0;
    bool colInt;
};

// One 4-col horizontal-conv item (R6 data path, verbatim).
__device__ __forceinline__ void stageA_item(const StageACtx& cx, const ull* w2, int item)
{
    const int r  = item >> 3;
    const int cb = (item & 7) << 2;
    const int gy = cx.y0 + r;
    ull mSD[4] = {0,0,0,0}, mPQ[4] = {0,0,0,0};

    if ((unsigned)gy < 512u) {
        ull sd[14];   // window values at gx = x0+cb+i, i = 0..13
        if (cx.colInt) {
            // aligned base: x0+cb-3 = 32*bx + cb - 8, multiple of 4
            const float4* q1 = (const float4*)(cx.p1 + (gy << 9) + cx.x0 + cb - 3);
            const float4* q2 = (const float4*)(cx.p2 + (gy << 9) + cx.x0 + cb - 3);
            float4 a0=__ldg(q1+0), a1=__ldg(q1+1), a2=__ldg(q1+2), a3=__ldg(q1+3), a4=__ldg(q1+4);
            float4 b0=__ldg(q2+0), b1=__ldg(q2+1), b2=__ldg(q2+2), b3=__ldg(q2+3), b4=__ldg(q2+4);
            float av[20], bv[20];
            av[0]=a0.x;av[1]=a0.y;av[2]=a0.z;av[3]=a0.w; av[4]=a1.x;av[5]=a1.y;av[6]=a1.z;av[7]=a1.w;
            av[8]=a2.x;av[9]=a2.y;av[10]=a2.z;av[11]=a2.w; av[12]=a3.x;av[13]=a3.y;av[14]=a3.z;av[15]=a3.w;
            av[16]=a4.x;av[17]=a4.y;av[18]=a4.z;av[19]=a4.w;
            bv[0]=b0.x;bv[1]=b0.y;bv[2]=b0.z;bv[3]=b0.w; bv[4]=b1.x;bv[5]=b1.y;bv[6]=b1.z;bv[7]=b1.w;
            bv[8]=b2.x;bv[9]=b2.y;bv[10]=b2.z;bv[11]=b2.w; bv[12]=b3.x;bv[13]=b3.y;bv[14]=b3.z;bv[15]=b3.w;
            bv[16]=b4.x;bv[17]=b4.y;bv[18]=b4.z;bv[19]=b4.w;
#pragma unroll
            for (int i = 0; i < 14; ++i) {
                // +3 offset: loaded base is x0+cb-3, window base is x0+cb
                float s = av[i+3] + bv[i+3];
                float d = av[i+3] - bv[i+3];
                PACK2(sd[i], s, d);
            }
        } else {
#pragma unroll
            for (int i = 0; i < 14; ++i) {
                const int gx = cx.x0 + cb + i;
                const bool in = (unsigned)gx < 512u;
                float a = in ? __ldg(cx.p1 + (gy << 9) + gx) : 0.f;
                float b = in ? __ldg(cx.p2 + (gy << 9) + gx) : 0.f;
                PACK2(sd[i], a + b, a - b);
            }
        }
        // SD half-pass
#pragma unroll
        for (int t = 0; t < 11; ++t) {
            const ull w = w2[t < 6 ? t : 10 - t];
#pragma unroll
            for (int c = 0; c < 4; ++c) FMA2(mSD[c], sd[c+t], w);
        }
        // square in place, PQ half-pass
#pragma unroll
        for (int i = 0; i < 14; ++i) SQ2(sd[i]);
#pragma unroll
        for (int t = 0; t < 11; ++t) {
            const ull w = w2[t < 6 ? t : 10 - t];
#pragma unroll
            for (int c = 0; c < 4; ++c) FMA2(mPQ[c], sd[c+t], w);
        }
    }
    ulonglong2* oSD = (ulonglong2*)(cx.hSD + r*HS + cb);
    ulonglong2* oPQ = (ulonglong2*)(cx.hPQ + r*HS + cb);
    oSD[0] = make_ulonglong2(mSD[0], mSD[1]);
    oSD[1] = make_ulonglong2(mSD[2], mSD[3]);
    oPQ[0] = make_ulonglong2(mPQ[0], mPQ[1]);
    oPQ[1] = make_ulonglong2(mPQ[2], mPQ[3]);
}

__global__ __launch_bounds__(256, 4) void ssim_main(
    const float* __restrict__ img1, const float* __restrict__ img2,
    float* __restrict__ out)
{
    extern __shared__ ull smem[];
    ull* hSD = smem;           // HMAP: h-blur of packed {S=a+b, D=a-b}
    ull* hPQ = hSD + HMAP;     // HMAP: h-blur of packed {S^2, D^2}
    __shared__ float red[8];

    // Packed {w,w} weights, 6 distinct by symmetry (pinned in registers)
    const float gwf[6] = {W0,W1,W2,W3,W4,W5};
    ull w2[6];
#pragma unroll
    for (int t = 0; t < 6; ++t)
        w2[t] = (ull)__float_as_uint(gwf[t]) * 0x100000001ull;

    const int tid = threadIdx.x;
    const int bx = blockIdx.x;
    const int p  = blockIdx.z;

    StageACtx cx;
    cx.p1 = img1 + (size_t)p * (512*512);
    cx.p2 = img2 + (size_t)p * (512*512);
    cx.hSD = hSD;
    cx.hPQ = hPQ;
    cx.x0 = bx * TW - 5;
    cx.y0 = blockIdx.y * TH - 5;
    cx.colInt = (bx >= 1) && (bx <= 14);

    // ---- Stage A: 592 items = 2 full passes + 80-thread tail ----
    stageA_item(cx, w2, tid);
    stageA_item(cx, w2, tid + 256);
    if (tid < 80)
        stageA_item(cx, w2, tid + 512);
    __syncthreads();

    // ---- Stage B: vertical conv (packed, sliding window) + SSIM, 8 rows/thread ----
    const int tx = tid & 31;
    const int tg = tid >> 5;
    const int r0 = tg << 3;

    ull accSD[8], accPQ[8];
#pragma unroll
    for (int rr = 0; rr < 8; ++rr) { accSD[rr] = 0ull; accPQ[rr] = 0ull; }

    const ull* bSD = hSD + tx;
    const ull* bPQ = hPQ + tx;
#pragma unroll
    for (int i = 0; i < 18; ++i) {
        const ull v1 = bSD[(r0+i)*HS];
        const ull v2 = bPQ[(r0+i)*HS];
#pragma unroll
        for (int rr = 0; rr < 8; ++rr) {
            const int t = i - rr;
            if (t >= 0 && t < 11) {
                const ull w = w2[t < 6 ? t : 10 - t];
                FMA2(accSD[rr], v1, w);
                FMA2(accPQ[rr], v2, w);
            }
        }
    }

    float local = 0.f;
#pragma unroll
    for (int rr = 0; rr < 8; ++rr) {
        const float2 sd = *(const float2*)&accSD[rr];
        const float2 pq = *(const float2*)&accPQ[rr];
        const float S = sd.x, D = sd.y, P = pq.x, Q = pq.y;
        const float S2h = 0.5f*(S*S), D2h = 0.5f*(D*D);
        const float u  = S2h - D2h;     // 2*mu1*mu2
        const float v  = S2h + D2h;     // mu1^2 + mu2^2
        const float pm = 0.5f*(P - Q);  // 2*E[xy]
        const float qm = 0.5f*(P + Q);  // E[x^2] + E[y^2]
        const float num = (u + SSIM_C1) * (pm - u + SSIM_C2);
        const float den = (v + SSIM_C1) * (qm - v + SSIM_C2);
        local += __fdividef(num, den);
    }

    // ---- Reduce: warp -> block -> global, last block finalizes ----
#pragma unroll
    for (int o = 16; o; o >>= 1)
        local += __shfl_xor_sync(0xffffffffu, local, o);
    if (tx == 0) red[tg] = local;
    __syncthreads();
    if (tid == 0) {
        float s = 0.f;
#pragma unroll
        for (int i = 0; i < 8; ++i) s += red[i];
        atomicAdd(&g_accum, (double)s);
        __threadfence();
        unsigned int v = atomicAdd(&g_count, 1u);
        if (v == NBLOCKS - 1u) {
            double tot = atomicAdd(&g_accum, 0.0);
            out[0] = (float)(tot * (1.0 / (96.0 * 512.0 * 512.0)));
            g_accum = 0.0;
            __threadfence();
            g_count = 0u;
        }
    }
}

extern "C" void kernel_launch(void* const* d_in, const int* in_sizes, int n_in,
                              void* d_out, int out_size)
{
    const float* img1 = (const float*)d_in[0];
    const float* img2 = (const float*)d_in[1];

    const int smem_bytes = 2 * HMAP * 8;   // 42,624 B -> 4 CTAs x 256 thr / SM
    cudaFuncSetAttribute(ssim_main, cudaFuncAttributeMaxDynamicSharedMemorySize, smem_bytes);

    dim3 grid(512/TW, 512/TH, 96);
    ssim_main<<<grid, 256, smem_bytes>>>(img1, img2, (float*)d_out);
}

// round 15
// speedup vs baseline: 1.0139x; 1.0139x over previous
#include <cuda_runtime.h>

#define TW 32
#define TH 64
#define IH 74          // TH + 10
#define HS 36          // map-pair stride in ull (float2) units; 288B rows
#define HMAP (IH*HS)   // ulls per map-pair
#define NBLOCKS (16*8*96)
#define SSIM_C1 (0.01f*0.01f)
#define SSIM_C2 (0.03f*0.03f)

typedef unsigned long long ull;

__device__ double g_accum = 0.0;
__device__ unsigned int g_count = 0u;

// Gaussian(sigma=1.5, ws=11) 1-D half-weights (symmetric), normalized.
#define W0 0.00102838f
#define W1 0.00759880f
#define W2 0.03600077f
#define W3 0.10936069f
#define W4 0.21300553f
#define W5 0.26601172f

#define FMA2(acc, a, b) asm("fma.rn.f32x2 %0, %1, %2, %0;" : "+l"(acc) : "l"(a), "l"(b))
#define SQ2(x)          asm("mul.rn.f32x2 %0, %0, %0;"     : "+l"(x))
#define PACK2(dst, lo, hi) asm("mov.b64 %0, {%1, %2};" : "=l"(dst) : "f"(lo), "f"(hi))

__global__ __launch_bounds__(256, 4) void ssim_main(
    const float* __restrict__ img1, const float* __restrict__ img2,
    float* __restrict__ out)
{
    extern __shared__ ull smem[];
    ull* hSD = smem;           // HMAP: h-blur of packed {S=a+b, D=a-b}
    ull* hPQ = hSD + HMAP;     // HMAP: h-blur of packed {S^2, D^2}
    __shared__ float red[8];

    // Packed {w,w} weights, 6 distinct by symmetry
    const float gwf[6] = {W0,W1,W2,W3,W4,W5};
    ull w2[6];
#pragma unroll
    for (int t = 0; t < 6; ++t)
        w2[t] = (ull)__float_as_uint(gwf[t]) * 0x100000001ull;

    const int tid = threadIdx.x;
    const int bx = blockIdx.x;
    const int p  = blockIdx.z;
    const float* p1 = img1 + (size_t)p * (512*512);
    const float* p2 = img2 + (size_t)p * (512*512);
    const int x0 = bx * TW - 5;
    const int y0 = blockIdx.y * TH - 5;
    const bool colInt = (bx >= 1) && (bx <= 14);

    // ---- Stage A: fused gmem load + horizontal conv (packed SD / PQ) ----
    // Output col c (0..3) of block cb covers gmem cols [x0+cb+c, x0+cb+c+10].
    for (int item = tid; item < IH*8; item += 256) {
        const int r  = item >> 3;
        const int cb = (item & 7) << 2;
        const int gy = y0 + r;
        ull mSD[4] = {0,0,0,0}, mPQ[4] = {0,0,0,0};

        if ((unsigned)gy < 512u) {
            ull sd[14];   // window values at gx = x0+cb+i, i = 0..13
            if (colInt) {
                // aligned base: x0+cb-3 = 32*bx + cb - 8, multiple of 4
                const float4* q1 = (const float4*)(p1 + (gy << 9) + x0 + cb - 3);
                const float4* q2 = (const float4*)(p2 + (gy << 9) + x0 + cb - 3);
                float4 a0=__ldg(q1+0), a1=__ldg(q1+1), a2=__ldg(q1+2), a3=__ldg(q1+3), a4=__ldg(q1+4);
                float4 b0=__ldg(q2+0), b1=__ldg(q2+1), b2=__ldg(q2+2), b3=__ldg(q2+3), b4=__ldg(q2+4);
                float av[20], bv[20];
                av[0]=a0.x;av[1]=a0.y;av[2]=a0.z;av[3]=a0.w; av[4]=a1.x;av[5]=a1.y;av[6]=a1.z;av[7]=a1.w;
                av[8]=a2.x;av[9]=a2.y;av[10]=a2.z;av[11]=a2.w; av[12]=a3.x;av[13]=a3.y;av[14]=a3.z;av[15]=a3.w;
                av[16]=a4.x;av[17]=a4.y;av[18]=a4.z;av[19]=a4.w;
                bv[0]=b0.x;bv[1]=b0.y;bv[2]=b0.z;bv[3]=b0.w; bv[4]=b1.x;bv[5]=b1.y;bv[6]=b1.z;bv[7]=b1.w;
                bv[8]=b2.x;bv[9]=b2.y;bv[10]=b2.z;bv[11]=b2.w; bv[12]=b3.x;bv[13]=b3.y;bv[14]=b3.z;bv[15]=b3.w;
                bv[16]=b4.x;bv[17]=b4.y;bv[18]=b4.z;bv[19]=b4.w;
#pragma unroll
                for (int i = 0; i < 14; ++i) {
                    // +3 offset: loaded base is x0+cb-3, window base is x0+cb
                    float s = av[i+3] + bv[i+3];
                    float d = av[i+3] - bv[i+3];
                    PACK2(sd[i], s, d);
                }
            } else {
#pragma unroll
                for (int i = 0; i < 14; ++i) {
                    const int gx = x0 + cb + i;
                    const bool in = (unsigned)gx < 512u;
                    float a = in ? __ldg(p1 + (gy << 9) + gx) : 0.f;
                    float b = in ? __ldg(p2 + (gy << 9) + gx) : 0.f;
                    PACK2(sd[i], a + b, a - b);
                }
            }
            // SD half-pass
#pragma unroll
            for (int t = 0; t < 11; ++t) {
                const ull w = w2[t < 6 ? t : 10 - t];
#pragma unroll
                for (int c = 0; c < 4; ++c) FMA2(mSD[c], sd[c+t], w);
            }
            // square in place, PQ half-pass
#pragma unroll
            for (int i = 0; i < 14; ++i) SQ2(sd[i]);
#pragma unroll
            for (int t = 0; t < 11; ++t) {
                const ull w = w2[t < 6 ? t : 10 - t];
#pragma unroll
                for (int c = 0; c < 4; ++c) FMA2(mPQ[c], sd[c+t], w);
            }
        }
        ull* oSD = hSD + r*HS + cb;
        ull* oPQ = hPQ + r*HS + cb;
        ((ulonglong2*)oSD)[0] = make_ulonglong2(mSD[0], mSD[1]);
        ((ulonglong2*)oSD)[1] = make_ulonglong2(mSD[2], mSD[3]);
        ((ulonglong2*)oPQ)[0] = make_ulonglong2(mPQ[0], mPQ[1]);
        ((ulonglong2*)oPQ)[1] = make_ulonglong2(mPQ[2], mPQ[3]);
    }
    __syncthreads();

    // ---- Stage B: vertical conv (packed, sliding window) + SSIM, 8 rows/thread ----
    const int tx = tid & 31;
    const int tg = tid >> 5;
    const int r0 = tg << 3;

    ull accSD[8], accPQ[8];
#pragma unroll
    for (int rr = 0; rr < 8; ++rr) { accSD[rr] = 0ull; accPQ[rr] = 0ull; }

    const ull* bSD = hSD + tx;
    const ull* bPQ = hPQ + tx;
#pragma unroll
    for (int i = 0; i < 18; ++i) {
        const ull v1 = bSD[(r0+i)*HS];
        const ull v2 = bPQ[(r0+i)*HS];
#pragma unroll
        for (int rr = 0; rr < 8; ++rr) {
            const int t = i - rr;
            if (t >= 0 && t < 11) {
                const ull w = w2[t < 6 ? t : 10 - t];
                FMA2(accSD[rr], v1, w);
                FMA2(accPQ[rr], v2, w);
            }
        }
    }

    float local = 0.f;
#pragma unroll
    for (int rr = 0; rr < 8; ++rr) {
        const float2 sd = *(const float2*)&accSD[rr];
        const float2 pq = *(const float2*)&accPQ[rr];
        const float S = sd.x, D = sd.y, P = pq.x, Q = pq.y;
        const float S2h = 0.5f*(S*S), D2h = 0.5f*(D*D);
        const float u  = S2h - D2h;     // 2*mu1*mu2
        const float v  = S2h + D2h;     // mu1^2 + mu2^2
        const float pm = 0.5f*(P - Q);  // 2*E[xy]
        const float qm = 0.5f*(P + Q);  // E[x^2] + E[y^2]
        const float num = (u + SSIM_C1) * (pm - u + SSIM_C2);
        const float den = (v + SSIM_C1) * (qm - v + SSIM_C2);
        local += __fdividef(num, den);
    }

    // ---- Reduce: warp -> block -> global, last block finalizes ----
#pragma unroll
    for (int o = 16; o; o >>= 1)
        local += __shfl_xor_sync(0xffffffffu, local, o);
    if (tx == 0) red[tg] = local;
    __syncthreads();
    if (tid == 0) {
        float s = 0.f;
#pragma unroll
        for (int i = 0; i < 8; ++i) s += red[i];
        atomicAdd(&g_accum, (double)s);
        __threadfence();
        unsigned int v = atomicAdd(&g_count, 1u);
        if (v == NBLOCKS - 1u) {
            double tot = atomicAdd(&g_accum, 0.0);
            out[0] = (float)(tot * (1.0 / (96.0 * 512.0 * 512.0)));
            g_accum = 0.0;
            __threadfence();
            g_count = 0u;
        }
    }
}

extern "C" void kernel_launch(void* const* d_in, const int* in_sizes, int n_in,
                              void* d_out, int out_size)
{
    const float* img1 = (const float*)d_in[0];
    const float* img2 = (const float*)d_in[1];

    const int smem_bytes = 2 * HMAP * 8;   // 42,624 B -> 4 CTAs x 256 thr / SM
    cudaFuncSetAttribute(ssim_main, cudaFuncAttributeMaxDynamicSharedMemorySize, smem_bytes);

    dim3 grid(512/TW, 512/TH, 96);
    ssim_main<<<grid, 256, smem_bytes>>>(img1, img2, (float*)d_out);
}

// round 16
// speedup vs baseline: 1.0151x; 1.0012x over previous
#include <cuda_runtime.h>

#define TW 32
#define TH 64
#define IH 74          // TH + 10
#define HS 36          // map-pair stride in ull (float2) units; 288B rows
#define HMAP (IH*HS)   // ulls per map-pair
#define NBLOCKS (16*8*96)
#define SSIM_C1 (0.01f*0.01f)
#define SSIM_C2 (0.03f*0.03f)

typedef unsigned long long ull;

__device__ double g_accum = 0.0;
__device__ unsigned int g_count = 0u;

// Gaussian(sigma=1.5, ws=11) 1-D half-weights (symmetric), normalized.
#define W0 0.00102838f
#define W1 0.00759880f
#define W2 0.03600077f
#define W3 0.10936069f
#define W4 0.21300553f
#define W5 0.26601172f

#define FMA2(acc, a, b) asm("fma.rn.f32x2 %0, %1, %2, %0;" : "+l"(acc) : "l"(a), "l"(b))
#define SQ2(x)          asm("mul.rn.f32x2 %0, %0, %0;"     : "+l"(x))
#define PACK2(dst, lo, hi) asm("mov.b64 %0, {%1, %2};" : "=l"(dst) : "f"(lo), "f"(hi))

__global__ __launch_bounds__(256, 4) void ssim_main(
    const float* __restrict__ img1, const float* __restrict__ img2,
    float* __restrict__ out)
{
    extern __shared__ ull smem[];
    ull* hSD = smem;           // HMAP: h-blur of packed {S=a+b, D=a-b}
    ull* hPQ = hSD + HMAP;     // HMAP: h-blur of packed {S^2, D^2}
    __shared__ float red[8];

    // Packed {w,w} weights, 6 distinct by symmetry
    const float gwf[6] = {W0,W1,W2,W3,W4,W5};
    ull w2[6];
#pragma unroll
    for (int t = 0; t < 6; ++t)
        w2[t] = (ull)__float_as_uint(gwf[t]) * 0x100000001ull;

    const int tid = threadIdx.x;
    const int bx = blockIdx.x;
    const int p  = blockIdx.z;
    const float* p1 = img1 + (size_t)p * (512*512);
    const float* p2 = img2 + (size_t)p * (512*512);
    const int x0 = bx * TW - 5;
    const int y0 = blockIdx.y * TH - 5;
    const bool colInt = (bx >= 1) && (bx <= 14);

    // ---- Stage A: fused gmem load + horizontal conv (packed SD / PQ) ----
    // Output col c (0..3) of block cb covers gmem cols [x0+cb+c, x0+cb+c+10].
    for (int item = tid; item < IH*8; item += 256) {
        const int r  = item >> 3;
        const int cb = (item & 7) << 2;
        const int gy = y0 + r;
        ull mSD[4] = {0,0,0,0}, mPQ[4] = {0,0,0,0};

        if ((unsigned)gy < 512u) {
            ull sd[14];   // window values at gx = x0+cb+i, i = 0..13
            if (colInt) {
                // aligned base: x0+cb-3 = 32*bx + cb - 8, multiple of 4
                const float4* q1 = (const float4*)(p1 + (gy << 9) + x0 + cb - 3);
                const float4* q2 = (const float4*)(p2 + (gy << 9) + x0 + cb - 3);
                float4 a0=__ldg(q1+0), a1=__ldg(q1+1), a2=__ldg(q1+2), a3=__ldg(q1+3), a4=__ldg(q1+4);
                float4 b0=__ldg(q2+0), b1=__ldg(q2+1), b2=__ldg(q2+2), b3=__ldg(q2+3), b4=__ldg(q2+4);
                float av[20], bv[20];
                av[0]=a0.x;av[1]=a0.y;av[2]=a0.z;av[3]=a0.w; av[4]=a1.x;av[5]=a1.y;av[6]=a1.z;av[7]=a1.w;
                av[8]=a2.x;av[9]=a2.y;av[10]=a2.z;av[11]=a2.w; av[12]=a3.x;av[13]=a3.y;av[14]=a3.z;av[15]=a3.w;
                av[16]=a4.x;av[17]=a4.y;av[18]=a4.z;av[19]=a4.w;
                bv[0]=b0.x;bv[1]=b0.y;bv[2]=b0.z;bv[3]=b0.w; bv[4]=b1.x;bv[5]=b1.y;bv[6]=b1.z;bv[7]=b1.w;
                bv[8]=b2.x;bv[9]=b2.y;bv[10]=b2.z;bv[11]=b2.w; bv[12]=b3.x;bv[13]=b3.y;bv[14]=b3.z;bv[15]=b3.w;
                bv[16]=b4.x;bv[17]=b4.y;bv[18]=b4.z;bv[19]=b4.w;
#pragma unroll
                for (int i = 0; i < 14; ++i) {
                    // +3 offset: loaded base is x0+cb-3, window base is x0+cb
                    float s = av[i+3] + bv[i+3];
                    float d = av[i+3] - bv[i+3];
                    PACK2(sd[i], s, d);
                }
            } else {
#pragma unroll
                for (int i = 0; i < 14; ++i) {
                    const int gx = x0 + cb + i;
                    const bool in = (unsigned)gx < 512u;
                    float a = in ? __ldg(p1 + (gy << 9) + gx) : 0.f;
                    float b = in ? __ldg(p2 + (gy << 9) + gx) : 0.f;
                    PACK2(sd[i], a + b, a - b);
                }
            }
            // SD half-pass
#pragma unroll
            for (int t = 0; t < 11; ++t) {
                const ull w = w2[t < 6 ? t : 10 - t];
#pragma unroll
                for (int c = 0; c < 4; ++c) FMA2(mSD[c], sd[c+t], w);
            }
            // square in place, PQ half-pass
#pragma unroll
            for (int i = 0; i < 14; ++i) SQ2(sd[i]);
#pragma unroll
            for (int t = 0; t < 11; ++t) {
                const ull w = w2[t < 6 ? t : 10 - t];
#pragma unroll
                for (int c = 0; c < 4; ++c) FMA2(mPQ[c], sd[c+t], w);
            }
        }
        ull* oSD = hSD + r*HS + cb;
        ull* oPQ = hPQ + r*HS + cb;
        ((ulonglong2*)oSD)[0] = make_ulonglong2(mSD[0], mSD[1]);
        ((ulonglong2*)oSD)[1] = make_ulonglong2(mSD[2], mSD[3]);
        ((ulonglong2*)oPQ)[0] = make_ulonglong2(mPQ[0], mPQ[1]);
        ((ulonglong2*)oPQ)[1] = make_ulonglong2(mPQ[2], mPQ[3]);
    }
    __syncthreads();

    // ---- Stage B: vertical conv (packed, sliding window) + SSIM, 8 rows/thread ----
    const int tx = tid & 31;
    const int tg = tid >> 5;
    const int r0 = tg << 3;

    ull accSD[8], accPQ[8];
#pragma unroll
    for (int rr = 0; rr < 8; ++rr) { accSD[rr] = 0ull; accPQ[rr] = 0ull; }

    const ull* bSD = hSD + tx;
    const ull* bPQ = hPQ + tx;
#pragma unroll
    for (int i = 0; i < 18; ++i) {
        const ull v1 = bSD[(r0+i)*HS];
        const ull v2 = bPQ[(r0+i)*HS];
#pragma unroll
        for (int rr = 0; rr < 8; ++rr) {
            const int t = i - rr;
            if (t >= 0 && t < 11) {
                const ull w = w2[t < 6 ? t : 10 - t];
                FMA2(accSD[rr], v1, w);
                FMA2(accPQ[rr], v2, w);
            }
        }
    }

    float local = 0.f;
#pragma unroll
    for (int rr = 0; rr < 8; ++rr) {
        const float2 sd = *(const float2*)&accSD[rr];
        const float2 pq = *(const float2*)&accPQ[rr];
        const float S = sd.x, D = sd.y, P = pq.x, Q = pq.y;
        const float S2h = 0.5f*(S*S), D2h = 0.5f*(D*D);
        const float u  = S2h - D2h;     // 2*mu1*mu2
        const float v  = S2h + D2h;     // mu1^2 + mu2^2
        const float pm = 0.5f*(P - Q);  // 2*E[xy]
        const float qm = 0.5f*(P + Q);  // E[x^2] + E[y^2]
        const float num = (u + SSIM_C1) * (pm - u + SSIM_C2);
        const float den = (v + SSIM_C1) * (qm - v + SSIM_C2);
        local += __fdividef(num, den);
    }

    // ---- Reduce: warp -> block -> global, last block finalizes ----
#pragma unroll
    for (int o = 16; o; o >>= 1)
        local += __shfl_xor_sync(0xffffffffu, local, o);
    if (tx == 0) red[tg] = local;
    __syncthreads();
    if (tid == 0) {
        float s = 0.f;
#pragma unroll
        for (int i = 0; i < 8; ++i) s += red[i];
        atomicAdd(&g_accum, (double)s);
        __threadfence();
        unsigned int v = atomicAdd(&g_count, 1u);
        if (v == NBLOCKS - 1u) {
            double tot = atomicAdd(&g_accum, 0.0);
            out[0] = (float)(tot * (1.0 / (96.0 * 512.0 * 512.0)));
            g_accum = 0.0;
            __threadfence();
            g_count = 0u;
        }
    }
}

extern "C" void kernel_launch(void* const* d_in, const int* in_sizes, int n_in,
                              void* d_out, int out_size)
{
    const float* img1 = (const float*)d_in[0];
    const float* img2 = (const float*)d_in[1];

    const int smem_bytes = 2 * HMAP * 8;   // 42,624 B -> 4 CTAs x 256 thr / SM
    cudaFuncSetAttribute(ssim_main, cudaFuncAttributeMaxDynamicSharedMemorySize, smem_bytes);

    dim3 grid(512/TW, 512/TH, 96);
    ssim_main<<<grid, 256, smem_bytes>>>(img1, img2, (float*)d_out);
}